// round 5
// baseline (speedup 1.0000x reference)
#include <cuda_runtime.h>

#define QLEN  1024
#define MLEN  1024
#define KLENN 2048
#define BATCH 4
#define NH    16
#define DH    64
#define DM    1024

// Scratch: no allocation allowed -> device globals (~104 MB).
__device__ float g_Q[BATCH*NH*QLEN*DH];
__device__ float g_K[BATCH*NH*KLENN*DH];
__device__ float g_V[BATCH*NH*KLENN*DH];
__device__ float g_R[NH*KLENN*DH];
__device__ float g_AV[QLEN*BATCH*DM];
__device__ float g_O[QLEN*BATCH*DM];

__device__ __forceinline__ float ex2(float x) {
    float y; asm("ex2.approx.ftz.f32 %0, %1;" : "=f"(y) : "f"(x)); return y;
}

// Shared 128x128x16 SGEMM mainloop. As/Bs are [16][128]; acc is 8x8.
__device__ __forceinline__ void gemm_core(
    const float* __restrict__ Arow, const float* __restrict__ B, int ldb, int n0,
    float (&acc)[8][8], float (*As)[128], float (*Bs)[128], int t)
{
    const int rm=(t>>4)<<3, rn=(t&15)<<3, ar=t>>1, ac=(t&1)<<3, br=t>>5, bc=(t&31)<<2;
    for (int kt = 0; kt < DM; kt += 16) {
        float4 a0 = *(const float4*)(Arow + kt + ac);
        float4 a1 = *(const float4*)(Arow + kt + ac + 4);
        float4 b0 = *(const float4*)(B + (size_t)(kt + br) * ldb + n0 + bc);
        float4 b1 = *(const float4*)(B + (size_t)(kt + br + 8) * ldb + n0 + bc);
        __syncthreads();
        As[ac+0][ar]=a0.x; As[ac+1][ar]=a0.y; As[ac+2][ar]=a0.z; As[ac+3][ar]=a0.w;
        As[ac+4][ar]=a1.x; As[ac+5][ar]=a1.y; As[ac+6][ar]=a1.z; As[ac+7][ar]=a1.w;
        *(float4*)&Bs[br][bc]   = b0;
        *(float4*)&Bs[br+8][bc] = b1;
        __syncthreads();
        #pragma unroll
        for (int kk = 0; kk < 16; kk++) {
            float4 x0 = *(const float4*)&As[kk][rm];
            float4 x1 = *(const float4*)&As[kk][rm+4];
            float4 y0 = *(const float4*)&Bs[kk][rn];
            float4 y1 = *(const float4*)&Bs[kk][rn+4];
            float xa[8] = {x0.x,x0.y,x0.z,x0.w,x1.x,x1.y,x1.z,x1.w};
            float yb[8] = {y0.x,y0.y,y0.z,y0.w,y1.x,y1.y,y1.z,y1.w};
            #pragma unroll
            for (int i = 0; i < 8; i++) {
                #pragma unroll
                for (int j = 0; j < 8; j++) acc[i][j] += xa[i] * yb[j];
            }
        }
    }
}

// GEMM 1: [mems;content] @ W_qkv, scatter -> g_Q/g_K/g_V.
__global__ __launch_bounds__(256)
void k_qkv(const float* __restrict__ content, const float* __restrict__ mems,
           const float* __restrict__ W)
{
    __shared__ float As[16][128], Bs[16][128];
    const int t = threadIdx.x, n0 = blockIdx.x<<7, m0 = blockIdx.y<<7;
    const int rm=(t>>4)<<3, rn=(t&15)<<3, ar=t>>1;
    const int mA = m0 + ar;
    const float* Arow = (mA < MLEN*BATCH) ? (mems + (size_t)mA*DM)
                                          : (content + (size_t)(mA - MLEN*BATCH)*DM);
    float acc[8][8];
    #pragma unroll
    for (int i = 0; i < 8; i++) {
        #pragma unroll
        for (int j = 0; j < 8; j++) acc[i][j] = 0.f;
    }
    gemm_core(Arow, W, 3072, n0, acc, As, Bs, t);

    #pragma unroll
    for (int y = 0; y < 8; y++) {
        int m = m0 + rm + y, row = m >> 2, bb = m & 3;
        #pragma unroll
        for (int xh = 0; xh < 2; xh++) {
            int col = n0 + rn + (xh<<2);
            int sec = col >> 10, nn = (col>>6)&15, dd = col & 63;
            float4 v = make_float4(acc[y][xh*4+0],acc[y][xh*4+1],acc[y][xh*4+2],acc[y][xh*4+3]);
            if (sec == 0) {
                if (row >= MLEN)
                    *(float4*)&g_Q[(((size_t)bb*NH+nn)*QLEN + (row-MLEN))*DH + dd] = v;
            } else if (sec == 1) {
                *(float4*)&g_K[(((size_t)bb*NH+nn)*KLENN + row)*DH + dd] = v;
            } else {
                *(float4*)&g_V[(((size_t)bb*NH+nn)*KLENN + row)*DH + dd] = v;
            }
        }
    }
}

// GEMM 2: rel_pos @ W_r -> g_R[n][m][d]
__global__ __launch_bounds__(256)
void k_rproj(const float* __restrict__ relpos, const float* __restrict__ W)
{
    __shared__ float As[16][128], Bs[16][128];
    const int t = threadIdx.x, n0 = blockIdx.x<<7, m0 = blockIdx.y<<7;
    const int rm=(t>>4)<<3, rn=(t&15)<<3, ar=t>>1;
    const float* Arow = relpos + (size_t)(m0 + ar)*DM;
    float acc[8][8];
    #pragma unroll
    for (int i = 0; i < 8; i++) {
        #pragma unroll
        for (int j = 0; j < 8; j++) acc[i][j] = 0.f;
    }
    gemm_core(Arow, W, DM, n0, acc, As, Bs, t);

    #pragma unroll
    for (int y = 0; y < 8; y++) {
        int m = m0 + rm + y;
        #pragma unroll
        for (int xh = 0; xh < 2; xh++) {
            int col = n0 + rn + (xh<<2), nn = col>>6, dd = col&63;
            float4 v = make_float4(acc[y][xh*4+0],acc[y][xh*4+1],acc[y][xh*4+2],acc[y][xh*4+3]);
            *(float4*)&g_R[((size_t)nn*KLENN + m)*DH + dd] = v;
        }
    }
}

// GEMM 3: g_AV @ W_o + content -> g_O
__global__ __launch_bounds__(256)
void k_out(const float* __restrict__ content, const float* __restrict__ W)
{
    __shared__ float As[16][128], Bs[16][128];
    const int t = threadIdx.x, n0 = blockIdx.x<<7, m0 = blockIdx.y<<7;
    const int rm=(t>>4)<<3, rn=(t&15)<<3, ar=t>>1;
    const float* Arow = g_AV + (size_t)(m0 + ar)*DM;
    float acc[8][8];
    #pragma unroll
    for (int i = 0; i < 8; i++) {
        #pragma unroll
        for (int j = 0; j < 8; j++) acc[i][j] = 0.f;
    }
    gemm_core(Arow, W, DM, n0, acc, As, Bs, t);

    #pragma unroll
    for (int y = 0; y < 8; y++) {
        size_t m = m0 + rm + y;
        #pragma unroll
        for (int xh = 0; xh < 2; xh++) {
            int col = n0 + rn + (xh<<2);
            float4 c4 = *(const float4*)(content + m*DM + col);
            float4 v = make_float4(acc[y][xh*4+0]+c4.x, acc[y][xh*4+1]+c4.y,
                                   acc[y][xh*4+2]+c4.z, acc[y][xh*4+3]+c4.w);
            *(float4*)&g_O[m*DM + col] = v;
        }
    }
}

// Fused flash attention with Transformer-XL rel-shift.
// Block = 64 q-rows x (head n, batch b). 256 thr, 16x16 grid, 4x4 microtile.
#define SMF_QA 0
#define SMF_QB 4096
#define SMF_KT 8192
#define SMF_VT 12288
#define SMF_RT 16384
#define SMF_PS 24576
#define SMEM_ATTN ((24576 + 64*68) * 4)

__global__ __launch_bounds__(256)
void k_attn(const float* __restrict__ rwb, const float* __restrict__ rrb)
{
    extern __shared__ float smf[];
    float* qaT = smf + SMF_QA;   // [64 d][64 il]
    float* qbT = smf + SMF_QB;   // [64 d][64 il]
    float* ktT = smf + SMF_KT;   // [64 d][64 jc]
    float* vt  = smf + SMF_VT;   // [64 jc][64 d]
    float* rtT = smf + SMF_RT;   // [64 d][128 rl]
    float* ps  = smf + SMF_PS;   // [64 il][68]

    const int t = threadIdx.x, lane = t&31, w = t>>5, tx = t&15, ty = t>>4;
    const int i0 = blockIdx.x<<6, n = blockIdx.y, b = blockIdx.z;

    const float* Qb = g_Q + (size_t)(b*NH+n)*QLEN*DH;
    const float* Kb = g_K + (size_t)(b*NH+n)*KLENN*DH;
    const float* Vb = g_V + (size_t)(b*NH+n)*KLENN*DH;
    const float* Rb = g_R + (size_t)n*KLENN*DH;

    {   // Q tile + both biases, transposed (d-major).
        int qrow = lane + ((w>>2)<<5);
        int d0 = (w&3)<<4;
        const float* qp = Qb + (size_t)(i0+qrow)*DH + d0;
        #pragma unroll
        for (int u = 0; u < 4; u++) {
            float4 v = *(const float4*)(qp + 4*u);
            int d = d0 + 4*u;
            qaT[(d+0)*64+qrow]=v.x+rwb[n*DH+d+0]; qbT[(d+0)*64+qrow]=v.x+rrb[n*DH+d+0];
            qaT[(d+1)*64+qrow]=v.y+rwb[n*DH+d+1]; qbT[(d+1)*64+qrow]=v.y+rrb[n*DH+d+1];
            qaT[(d+2)*64+qrow]=v.z+rwb[n*DH+d+2]; qbT[(d+2)*64+qrow]=v.z+rrb[n*DH+d+2];
            qaT[(d+3)*64+qrow]=v.w+rwb[n*DH+d+3]; qbT[(d+3)*64+qrow]=v.w+rrb[n*DH+d+3];
        }
    }

    float mrow[4], lrow[4], o[4][4];
    #pragma unroll
    for (int a = 0; a < 4; a++) {
        mrow[a] = -1e30f; lrow[a] = 0.f;
        #pragma unroll
        for (int c = 0; c < 4; c++) o[a][c] = 0.f;
    }

    const float fscale = 0.18033688011112042f;  // (1/sqrt(64))*log2(e)
    const int ntiles = (i0>>6) + 17;
    const int rb4 = ((tx - ty)<<2) + 60;        // 0..120

    for (int tile = 0; tile < ntiles; tile++) {
        const int j0 = tile<<6;
        __syncthreads();
        {   // K tile transposed
            int jc = lane + ((w>>2)<<5); int d0 = (w&3)<<4;
            const float* kp = Kb + (size_t)(j0+jc)*DH + d0;
            #pragma unroll
            for (int u = 0; u < 4; u++) {
                float4 v = *(const float4*)(kp + 4*u); int d = d0 + 4*u;
                ktT[(d+0)*64+jc]=v.x; ktT[(d+1)*64+jc]=v.y;
                ktT[(d+2)*64+jc]=v.z; ktT[(d+3)*64+jc]=v.w;
            }
        }
        {   // V tile row-major
            int jc = t>>2; int d0 = (t&3)<<4;
            const float* vp = Vb + (size_t)(j0+jc)*DH + d0;
            #pragma unroll
            for (int u = 0; u < 4; u++)
                *(float4*)&vt[jc*64 + d0 + 4*u] = *(const float4*)(vp + 4*u);
        }
        {   // R window (128 rows), transposed; OOB rows -> 0 (masked anyway)
            int rr = lane + ((w>>1)<<5); int d0 = (w&1)<<5;
            int mg = j0 + 960 - i0 + rr;
            #pragma unroll
            for (int u = 0; u < 8; u++) {
                int d = d0 + 4*u;
                float4 v = make_float4(0.f,0.f,0.f,0.f);
                if (mg < KLENN) v = *(const float4*)(Rb + (size_t)mg*DH + d);
                rtT[(d+0)*128+rr]=v.x; rtT[(d+1)*128+rr]=v.y;
                rtT[(d+2)*128+rr]=v.z; rtT[(d+3)*128+rr]=v.w;
            }
        }
        __syncthreads();

        // Scores: AC + rel-shifted BD. rl = rb4 + (c - a + 3)
        float acc[4][4];
        #pragma unroll
        for (int a = 0; a < 4; a++) {
            #pragma unroll
            for (int c = 0; c < 4; c++) acc[a][c] = 0.f;
        }
        #pragma unroll 8
        for (int d = 0; d < 64; d++) {
            float4 qa4 = *(const float4*)&qaT[d*64 + (ty<<2)];
            float4 qb4 = *(const float4*)&qbT[d*64 + (ty<<2)];
            float4 kk4 = *(const float4*)&ktT[d*64 + (tx<<2)];
            float4 r04 = *(const float4*)&rtT[d*128 + rb4];
            float4 r14 = *(const float4*)&rtT[d*128 + rb4 + 4];
            float qaa[4]={qa4.x,qa4.y,qa4.z,qa4.w};
            float qbb[4]={qb4.x,qb4.y,qb4.z,qb4.w};
            float kkk[4]={kk4.x,kk4.y,kk4.z,kk4.w};
            float rr7[7]={r04.x,r04.y,r04.z,r04.w,r14.x,r14.y,r14.z};
            #pragma unroll
            for (int a = 0; a < 4; a++) {
                #pragma unroll
                for (int c = 0; c < 4; c++)
                    acc[a][c] += qaa[a]*kkk[c] + qbb[a]*rr7[c-a+3];
            }
        }

        // Online softmax (exp2 domain); row max reduced across the 16-lane tx group
        #pragma unroll
        for (int a = 0; a < 4; a++) {
            const int iq = i0 + (ty<<2) + a;
            float s[4];
            #pragma unroll
            for (int c = 0; c < 4; c++) {
                int jk = j0 + (tx<<2) + c;
                s[c] = (jk > iq + MLEN) ? -1e30f : acc[a][c]*fscale;
            }
            float tm = fmaxf(fmaxf(s[0],s[1]), fmaxf(s[2],s[3]));
            tm = fmaxf(tm, __shfl_xor_sync(0xffffffffu, tm, 8));
            tm = fmaxf(tm, __shfl_xor_sync(0xffffffffu, tm, 4));
            tm = fmaxf(tm, __shfl_xor_sync(0xffffffffu, tm, 2));
            tm = fmaxf(tm, __shfl_xor_sync(0xffffffffu, tm, 1));
            float mn = fmaxf(mrow[a], tm);
            float cf = ex2(mrow[a] - mn);
            mrow[a] = mn;
            float p0=ex2(s[0]-mn), p1=ex2(s[1]-mn), p2=ex2(s[2]-mn), p3=ex2(s[3]-mn);
            lrow[a] = lrow[a]*cf + (p0+p1+p2+p3);
            #pragma unroll
            for (int c = 0; c < 4; c++) o[a][c] *= cf;
            *(float4*)&ps[((ty<<2)+a)*68 + (tx<<2)] = make_float4(p0,p1,p2,p3);
        }
        __syncthreads();

        // PV: o[a][c] += sum_j ps[row][j] * vt[j][tx*4+c]
        #pragma unroll 4
        for (int j = 0; j < 64; j++) {
            float4 v4 = *(const float4*)&vt[j*64 + (tx<<2)];
            #pragma unroll
            for (int a = 0; a < 4; a++) {
                float pa = ps[((ty<<2)+a)*68 + j];
                o[a][0] += pa*v4.x; o[a][1] += pa*v4.y;
                o[a][2] += pa*v4.z; o[a][3] += pa*v4.w;
            }
        }
    }

    // Normalize (l reduced across tx group) and store to g_AV[i][b][n*64+d]
    #pragma unroll
    for (int a = 0; a < 4; a++) {
        float lt = lrow[a];
        lt += __shfl_xor_sync(0xffffffffu, lt, 8);
        lt += __shfl_xor_sync(0xffffffffu, lt, 4);
        lt += __shfl_xor_sync(0xffffffffu, lt, 2);
        lt += __shfl_xor_sync(0xffffffffu, lt, 1);
        float inv = 1.f / lt;
        float4 v = make_float4(o[a][0]*inv, o[a][1]*inv, o[a][2]*inv, o[a][3]*inv);
        size_t row = (size_t)(i0 + (ty<<2) + a)*BATCH + b;
        *(float4*)&g_AV[row*DM + n*DH + (tx<<2)] = v;
    }
}

// LayerNorm over g_O rows -> d_out
__global__ __launch_bounds__(256)
void k_ln(const float* __restrict__ gamma, const float* __restrict__ beta,
          float* __restrict__ out)
{
    __shared__ float red[16];
    const int t = threadIdx.x;
    const size_t row = blockIdx.x;
    float4 x = *(const float4*)&g_O[row*DM + t*4];
    float s = x.x + x.y + x.z + x.w;
    float ss = x.x*x.x + x.y*x.y + x.z*x.z + x.w*x.w;
    #pragma unroll
    for (int m = 16; m > 0; m >>= 1) {
        s  += __shfl_xor_sync(0xffffffffu, s, m);
        ss += __shfl_xor_sync(0xffffffffu, ss, m);
    }
    if ((t&31) == 0) { red[t>>5] = s; red[8 + (t>>5)] = ss; }
    __syncthreads();
    if (t < 8) {
        float a = red[t], bsum = red[8+t];
        #pragma unroll
        for (int m = 4; m > 0; m >>= 1) {
            a    += __shfl_xor_sync(0xffu, a, m);
            bsum += __shfl_xor_sync(0xffu, bsum, m);
        }
        if (t == 0) { red[0] = a; red[8] = bsum; }
    }
    __syncthreads();
    float mu = red[0] * (1.f/DM);
    float var = red[8] * (1.f/DM) - mu*mu;
    float rs = rsqrtf(var + 1e-5f);
    float4 g = *(const float4*)&gamma[t*4];
    float4 be = *(const float4*)&beta[t*4];
    float4 y;
    y.x = (x.x-mu)*rs*g.x + be.x;
    y.y = (x.y-mu)*rs*g.y + be.y;
    y.z = (x.z-mu)*rs*g.z + be.z;
    y.w = (x.w-mu)*rs*g.w + be.w;
    *(float4*)&out[row*DM + t*4] = y;
}

extern "C" void kernel_launch(void* const* d_in, const int* in_sizes, int n_in,
                              void* d_out, int out_size)
{
    const float* content = (const float*)d_in[0];
    const float* rel_pos = (const float*)d_in[1];
    const float* mems    = (const float*)d_in[2];
    const float* rwb     = (const float*)d_in[3];
    const float* rrb     = (const float*)d_in[4];
    const float* Wqkv    = (const float*)d_in[5];
    const float* Wr      = (const float*)d_in[6];
    const float* Wo      = (const float*)d_in[7];
    const float* gamma   = (const float*)d_in[8];
    const float* beta    = (const float*)d_in[9];
    float* out = (float*)d_out;

    cudaFuncSetAttribute(k_attn, cudaFuncAttributeMaxDynamicSharedMemorySize, SMEM_ATTN);

    k_qkv  <<<dim3(24, 64), 256>>>(content, mems, Wqkv);
    k_rproj<<<dim3(8, 16),  256>>>(rel_pos, Wr);
    k_attn <<<dim3(QLEN/64, NH, BATCH), 256, SMEM_ATTN>>>(rwb, rrb);
    k_out  <<<dim3(8, 32),  256>>>(content, Wo);
    k_ln   <<<QLEN*BATCH, 256>>>(gamma, beta, out);
}